// round 1
// baseline (speedup 1.0000x reference)
#include <cuda_runtime.h>
#include <cstdint>

#define B_TOK 16384
#define N_CB  8192
#define DIM   512

#define TM 128
#define TN 128
#define TK 16
#define NTHREADS 256

// Scratch for codebook squared norms (no cudaMalloc allowed).
__device__ float g_c2[N_CB];

// ---------------------------------------------------------------------------
// Kernel 1: c2[n] = sum_k codebook[n][k]^2   (one warp per row)
// ---------------------------------------------------------------------------
__global__ void c2_kernel(const float* __restrict__ cb) {
    int row  = blockIdx.x * blockDim.y + threadIdx.y;
    int lane = threadIdx.x;
    const float4* r = (const float4*)(cb + (size_t)row * DIM);
    float s = 0.f;
#pragma unroll
    for (int i = 0; i < 4; i++) {
        float4 v = r[lane + 32 * i];
        s += v.x * v.x + v.y * v.y + v.z * v.z + v.w * v.w;
    }
#pragma unroll
    for (int off = 16; off > 0; off >>= 1)
        s += __shfl_down_sync(0xFFFFFFFFu, s, off);
    if (lane == 0) g_c2[row] = s;
}

// Pack (score, index) so that u64 max == (max score, then min index).
__device__ __forceinline__ unsigned long long pack_key(float t, unsigned n) {
    unsigned u = __float_as_uint(t);
    u = (u & 0x80000000u) ? ~u : (u | 0x80000000u);   // order-preserving map
    return ((unsigned long long)u << 32) | (unsigned long long)(0xFFFFFFFFu - n);
}

// ---------------------------------------------------------------------------
// Kernel 2: fused  scores = 2*x@cb^T - c2  ->  argmax per token  ->  gather
// Block: 128 tokens. Loop over all 8192 codes in 128-wide tiles.
// ---------------------------------------------------------------------------
__global__ __launch_bounds__(NTHREADS, 1)
void vq_kernel(const float* __restrict__ x,
               const float* __restrict__ cb,
               const float* __restrict__ emb,
               float* __restrict__ out) {
    __shared__ float As[TK][TM + 4];   // stride 132 floats (528B, 16B aligned)
    __shared__ float Bs[TK][TN + 4];
    __shared__ unsigned long long best[TM];
    __shared__ float c2s[TN];

    const int tid = threadIdx.x;
    const int tx  = tid & 15;          // n-dim group
    const int ty  = tid >> 4;          // m-dim group
    const int m0  = blockIdx.x * TM;

    for (int i = tid; i < TM; i += NTHREADS) best[i] = 0ULL;

    for (int n0 = 0; n0 < N_CB; n0 += TN) {
        __syncthreads();               // prior tile's c2s/best reads done
        if (tid < TN) c2s[tid] = g_c2[n0 + tid];

        float acc[8][8];
#pragma unroll
        for (int i = 0; i < 8; i++)
#pragma unroll
            for (int j = 0; j < 8; j++) acc[i][j] = 0.f;

        for (int k0 = 0; k0 < DIM; k0 += TK) {
            __syncthreads();           // previous compute done before overwrite
#pragma unroll
            for (int j = 0; j < 2; j++) {
                int i  = tid + NTHREADS * j;
                int m  = i >> 2;
                int kk = (i & 3) * 4;
                float4 va = *(const float4*)&x [(size_t)(m0 + m) * DIM + k0 + kk];
                As[kk + 0][m] = va.x; As[kk + 1][m] = va.y;
                As[kk + 2][m] = va.z; As[kk + 3][m] = va.w;
                float4 vb = *(const float4*)&cb[(size_t)(n0 + m) * DIM + k0 + kk];
                Bs[kk + 0][m] = vb.x; Bs[kk + 1][m] = vb.y;
                Bs[kk + 2][m] = vb.z; Bs[kk + 3][m] = vb.w;
            }
            __syncthreads();

#pragma unroll
            for (int k = 0; k < TK; k++) {
                float a[8], b[8];
                *(float4*)&a[0] = *(const float4*)&As[k][ty * 4];
                *(float4*)&a[4] = *(const float4*)&As[k][64 + ty * 4];
                *(float4*)&b[0] = *(const float4*)&Bs[k][tx * 4];
                *(float4*)&b[4] = *(const float4*)&Bs[k][64 + tx * 4];
#pragma unroll
                for (int i = 0; i < 8; i++)
#pragma unroll
                    for (int j = 0; j < 8; j++)
                        acc[i][j] = fmaf(a[i], b[j], acc[i][j]);
            }
        }

        // Fused argmax update: t = 2*s - c2  (argmax t == argmin L2 distance)
#pragma unroll
        for (int i = 0; i < 8; i++) {
            int m = (i < 4) ? (ty * 4 + i) : (64 + ty * 4 + (i - 4));
            unsigned long long k_best = 0ULL;
#pragma unroll
            for (int j = 0; j < 8; j++) {
                int nl = (j < 4) ? (tx * 4 + j) : (64 + tx * 4 + (j - 4));
                float t = fmaf(2.0f, acc[i][j], -c2s[nl]);
                unsigned long long key = pack_key(t, (unsigned)(n0 + nl));
                if (key > k_best) k_best = key;
            }
            atomicMax(&best[m], k_best);
        }
    }
    __syncthreads();

    // Gather: out[m] = embedding[idx[m]]  (float4 vectorized)
    const float4* e4 = (const float4*)emb;
    float4* o4 = (float4*)out;
    const int C4 = DIM / 4;
    for (int i = tid; i < TM * C4; i += NTHREADS) {
        int m = i / C4;
        int c = i % C4;
        unsigned idx = 0xFFFFFFFFu - (unsigned)(best[m] & 0xFFFFFFFFu);
        o4[(size_t)(m0 + m) * C4 + c] = e4[(size_t)idx * C4 + c];
    }
}

// ---------------------------------------------------------------------------
extern "C" void kernel_launch(void* const* d_in, const int* in_sizes, int n_in,
                              void* d_out, int out_size) {
    const float* x   = (const float*)d_in[0];   // (16384, 512)
    const float* cb  = (const float*)d_in[1];   // (8192, 512)
    const float* emb = (const float*)d_in[2];   // (8192, 512)
    float* out = (float*)d_out;                 // (16384, 512)

    c2_kernel<<<N_CB / 8, dim3(32, 8)>>>(cb);
    vq_kernel<<<B_TOK / TM, NTHREADS>>>(x, cb, emb, out);
}

// round 5
// speedup vs baseline: 5.1353x; 5.1353x over previous
#include <cuda_runtime.h>
#include <cuda_fp16.h>
#include <cstdint>

#define B_TOK 16384
#define N_CB  8192
#define DIM   512
#define MT    128          // tokens per CTA
#define NTILE 128          // codes per n-tile
#define KCH   64           // k per chunk
#define KCHUNKS 8          // DIM/KCH
#define TILES (N_CB/NTILE) // 64
#define NTHREADS 256
#define MARGIN 0.25f
#define CAP   32

// ---- global scratch (no cudaMalloc allowed) ----
__device__ __align__(128) __half g_xh[B_TOK * DIM];
__device__ __align__(128) __half g_ch[N_CB * DIM];
__device__ __align__(128) float  g_c2[N_CB];

// ---- SMEM layout (bytes) ----
#define SM_C2   0          // 128 f32
#define SM_MAX  512        // 128 u32 running max (encoded)
#define SM_CNT  1024       // 128 u32 candidate counts
#define SM_IDX  1536       // 128 u32 final indices
#define SM_LST  2048       // 128 * CAP u32 = 16384
#define SM_A    18432      // 8 chunks x [128 x 64] half (SW128) = 131072
#define SM_B    149504     // 2 bufs x 16384 = 32768
#define SMEM_TOTAL 182272

// ---------------- helpers ----------------
__device__ __forceinline__ uint32_t smem_u32(const void* p) {
    uint32_t a;
    asm("{ .reg .u64 t; cvta.to.shared.u64 t, %1; cvt.u32.u64 %0, t; }" : "=r"(a) : "l"(p));
    return a;
}
__device__ __forceinline__ void cpa16(uint32_t dst, const void* src) {
    asm volatile("cp.async.cg.shared.global [%0], [%1], 16;" :: "r"(dst), "l"(src));
}
__device__ __forceinline__ void cpa_commit() { asm volatile("cp.async.commit_group;" ::: "memory"); }
__device__ __forceinline__ void cpa_wait0()  { asm volatile("cp.async.wait_group 0;"  ::: "memory"); }

__device__ __forceinline__ void ldsm4(uint32_t* r, uint32_t addr) {
    asm volatile("ldmatrix.sync.aligned.m8n8.x4.shared.b16 {%0,%1,%2,%3}, [%4];"
                 : "=r"(r[0]), "=r"(r[1]), "=r"(r[2]), "=r"(r[3]) : "r"(addr));
}
__device__ __forceinline__ void mma16816(float* d, const uint32_t* a, uint32_t b0, uint32_t b1) {
    asm volatile("mma.sync.aligned.m16n8k16.row.col.f32.f16.f16.f32 "
                 "{%0,%1,%2,%3}, {%4,%5,%6,%7}, {%8,%9}, {%0,%1,%2,%3};"
                 : "+f"(d[0]), "+f"(d[1]), "+f"(d[2]), "+f"(d[3])
                 : "r"(a[0]), "r"(a[1]), "r"(a[2]), "r"(a[3]), "r"(b0), "r"(b1));
}

__device__ __forceinline__ uint32_t sw128(uint32_t off) { return off ^ ((off >> 3) & 0x70); }

__device__ __forceinline__ uint32_t enc32(float s) {
    uint32_t u = __float_as_uint(s);
    return (u & 0x80000000u) ? ~u : (u | 0x80000000u);
}
__device__ __forceinline__ float dec32(uint32_t v) {
    return (v & 0x80000000u) ? __uint_as_float(v ^ 0x80000000u) : __uint_as_float(~v);
}
__device__ __forceinline__ unsigned long long pack_key(float t, unsigned n) {
    return ((unsigned long long)enc32(t) << 32) | (unsigned long long)(0xFFFFFFFFu - n);
}

// ---------------- pre-kernels ----------------
__global__ void c2_kernel(const float* __restrict__ cb) {
    int row  = blockIdx.x * blockDim.y + threadIdx.y;
    int lane = threadIdx.x;
    const float4* r = (const float4*)(cb + (size_t)row * DIM);
    float s = 0.f;
#pragma unroll
    for (int i = 0; i < 4; i++) {
        float4 v = r[lane + 32 * i];
        s += v.x*v.x + v.y*v.y + v.z*v.z + v.w*v.w;
    }
#pragma unroll
    for (int off = 16; off > 0; off >>= 1) s += __shfl_down_sync(0xFFFFFFFFu, s, off);
    if (lane == 0) g_c2[row] = s;
}

__global__ void tohalf_kernel(const float* __restrict__ src, __half* __restrict__ dst, int n4) {
    int i = blockIdx.x * blockDim.x + threadIdx.x;
    if (i >= n4) return;
    float4 v = ((const float4*)src)[i];
    __half2 h0 = __floats2half2_rn(v.x, v.y);
    __half2 h1 = __floats2half2_rn(v.z, v.w);
    ((__half2*)dst)[2*i]   = h0;
    ((__half2*)dst)[2*i+1] = h1;
}

// ---------------- main fused kernel ----------------
__global__ __launch_bounds__(NTHREADS, 1)
void vq_kernel(const float* __restrict__ x, const float* __restrict__ cb,
               const float* __restrict__ emb, float* __restrict__ out) {
    extern __shared__ char smem[];
    const uint32_t sb = smem_u32(smem);
    const int tid  = threadIdx.x;
    const int wid  = tid >> 5;
    const int lane = tid & 31;
    const int m0   = blockIdx.x * MT;
    const int wm   = wid & 1;       // m-group: rows wm*64 .. +63
    const int wn   = wid >> 1;      // n-group: cols wn*32 .. +31

    float*    c2s  = (float*)(smem + SM_C2);
    uint32_t* rmax = (uint32_t*)(smem + SM_MAX);
    uint32_t* cnt  = (uint32_t*)(smem + SM_CNT);
    uint32_t* idxs = (uint32_t*)(smem + SM_IDX);
    uint32_t* lst  = (uint32_t*)(smem + SM_LST);

    if (tid < MT) { rmax[tid] = 0u; cnt[tid] = 0u; }

    // ---- load A (x fp16) into SMEM: 8 chunks of [128 x 64] SW128 ----
    for (int i = tid; i < KCHUNKS * MT * 8; i += NTHREADS) {   // 16B units
        int ch = i >> 10, rem = i & 1023, r = rem >> 3, u = rem & 7;
        cpa16(sb + SM_A + ch * 16384 + sw128(r * 128 + u * 16),
              g_xh + ((size_t)(m0 + r) * DIM + ch * KCH + u * 8));
    }
    cpa_commit();

    // per-thread ldmatrix address components (byte offsets inside a chunk)
    const int rowA[4] = { wm*64 + 0*16 + (lane & 15), wm*64 + 1*16 + (lane & 15),
                          wm*64 + 2*16 + (lane & 15), wm*64 + 3*16 + (lane & 15) };
    const int kuA = (lane >> 4) * 16;                       // 0 or 16 bytes
    const int rowB = wn*32 + (lane & 7) + ((lane >> 4) << 3); // covers 16 n-rows via x4
    const int kuB = ((lane >> 3) & 1) * 16;

    float acc[4][4][4];

    for (int t = 0; t < TILES; t++) {
        // prefetch B chunk 0
        {
            uint32_t dst = sb + SM_B;
            const __half* src = g_ch + (size_t)(t * NTILE) * DIM;
#pragma unroll
            for (int j = 0; j < 4; j++) {
                int i = tid * 4 + j, r = i >> 3, u = i & 7;
                cpa16(dst + sw128(r * 128 + u * 16), src + (size_t)r * DIM + u * 8);
            }
            cpa_commit();
        }
        if (tid < NTILE) c2s[tid] = g_c2[t * NTILE + tid];

#pragma unroll
        for (int mf = 0; mf < 4; mf++)
#pragma unroll
            for (int nf = 0; nf < 4; nf++)
#pragma unroll
                for (int k = 0; k < 4; k++) acc[mf][nf][k] = 0.f;

        for (int c = 0; c < KCHUNKS; c++) {
            cpa_wait0();
            __syncthreads();                     // chunk c visible to all
            if (c + 1 < KCHUNKS) {               // prefetch next chunk
                uint32_t dst = sb + SM_B + ((c + 1) & 1) * 16384;
                const __half* src = g_ch + (size_t)(t * NTILE) * DIM + (c + 1) * KCH;
#pragma unroll
                for (int j = 0; j < 4; j++) {
                    int i = tid * 4 + j, r = i >> 3, u = i & 7;
                    cpa16(dst + sw128(r * 128 + u * 16), src + (size_t)r * DIM + u * 8);
                }
                cpa_commit();
            }
            uint32_t abase = sb + SM_A + c * 16384;
            uint32_t bbase = sb + SM_B + (c & 1) * 16384;
#pragma unroll
            for (int ks = 0; ks < 4; ks++) {
                uint32_t a[4][4], b[2][4];
#pragma unroll
                for (int mf = 0; mf < 4; mf++)
                    ldsm4(a[mf], abase + sw128(rowA[mf] * 128 + ks * 32 + kuA));
#pragma unroll
                for (int g = 0; g < 2; g++)
                    ldsm4(b[g], bbase + sw128((rowB + g * 16) * 128 + ks * 32 + kuB));
#pragma unroll
                for (int mf = 0; mf < 4; mf++)
#pragma unroll
                    for (int nf = 0; nf < 4; nf++)
                        mma16816(acc[mf][nf], a[mf],
                                 b[nf >> 1][(nf & 1) * 2], b[nf >> 1][(nf & 1) * 2 + 1]);
            }
        }
        __syncthreads();                          // all MMAs done; c2s visible

        // ---- epilogue: running max ----
#pragma unroll
        for (int mf = 0; mf < 4; mf++)
#pragma unroll
            for (int rr = 0; rr < 2; rr++) {
                int row = wm*64 + mf*16 + (lane >> 2) + rr*8;
                float rb = -3.4e38f;
#pragma unroll
                for (int nf = 0; nf < 4; nf++)
#pragma unroll
                    for (int cc = 0; cc < 2; cc++) {
                        int col = wn*32 + nf*8 + (lane & 3)*2 + cc;
                        float s = fmaf(2.f, acc[mf][nf][rr*2 + cc], -c2s[col]);
                        if (s > rb) rb = s;
                    }
                atomicMax(&rmax[row], enc32(rb));
            }
        __syncthreads();

        // ---- admission: candidates within MARGIN of running max ----
#pragma unroll
        for (int mf = 0; mf < 4; mf++)
#pragma unroll
            for (int rr = 0; rr < 2; rr++) {
                int row = wm*64 + mf*16 + (lane >> 2) + rr*8;
                float thr = dec32(rmax[row]) - MARGIN;
#pragma unroll
                for (int nf = 0; nf < 4; nf++)
#pragma unroll
                    for (int cc = 0; cc < 2; cc++) {
                        int col = wn*32 + nf*8 + (lane & 3)*2 + cc;
                        float s = fmaf(2.f, acc[mf][nf][rr*2 + cc], -c2s[col]);
                        if (s >= thr) {
                            uint32_t slot = atomicAdd(&cnt[row], 1u);
                            if (slot < CAP) lst[row * CAP + slot] = (uint32_t)(t * NTILE + col);
                        }
                    }
            }
        __syncthreads();
    }

    // ---- phase 2: exact fp32 rescore of candidates ----
    for (int row = wid; row < MT; row += 8) {
        unsigned n = cnt[row];
        unsigned long long bestk = 0ULL;
        const float* xr = x + (size_t)(m0 + row) * DIM;
        if (n == 0 || n > CAP) {
            for (int code = 0; code < N_CB; code++) {     // exact fallback (never on this data)
                const float* cr = cb + (size_t)code * DIM;
                float p = 0.f;
                for (int e = lane; e < DIM; e += 32) p = fmaf(xr[e], cr[e], p);
#pragma unroll
                for (int off = 16; off > 0; off >>= 1) p += __shfl_xor_sync(0xFFFFFFFFu, p, off);
                unsigned long long k = pack_key(fmaf(2.f, p, -g_c2[code]), (unsigned)code);
                if (k > bestk) bestk = k;
            }
        } else {
            for (unsigned j = 0; j < n; j++) {
                unsigned code = lst[row * CAP + j];
                const float* cr = cb + (size_t)code * DIM;
                float p = 0.f;
#pragma unroll
                for (int e = 0; e < DIM / 32; e++) p = fmaf(xr[lane + 32*e], cr[lane + 32*e], p);
#pragma unroll
                for (int off = 16; off > 0; off >>= 1) p += __shfl_xor_sync(0xFFFFFFFFu, p, off);
                unsigned long long k = pack_key(fmaf(2.f, p, -g_c2[code]), code);
                if (k > bestk) bestk = k;
            }
        }
        if (lane == 0) idxs[row] = 0xFFFFFFFFu - (uint32_t)(bestk & 0xFFFFFFFFu);
    }
    __syncthreads();

    // ---- gather: out[m] = embedding[idx[m]] ----
    const float4* e4 = (const float4*)emb;
    float4* o4 = (float4*)out;
    for (int i = tid; i < MT * (DIM / 4); i += NTHREADS) {
        int m = i >> 7, cc = i & 127;
        o4[(size_t)(m0 + m) * (DIM / 4) + cc] = e4[(size_t)idxs[m] * (DIM / 4) + cc];
    }
}

// ---------------------------------------------------------------------------
extern "C" void kernel_launch(void* const* d_in, const int* in_sizes, int n_in,
                              void* d_out, int out_size) {
    const float* x   = (const float*)d_in[0];
    const float* cb  = (const float*)d_in[1];
    const float* emb = (const float*)d_in[2];
    float* out = (float*)d_out;

    cudaFuncSetAttribute(vq_kernel, cudaFuncAttributeMaxDynamicSharedMemorySize, SMEM_TOTAL);

    __half *xh, *ch;
    cudaGetSymbolAddress((void**)&xh, g_xh);
    cudaGetSymbolAddress((void**)&ch, g_ch);

    tohalf_kernel<<<(B_TOK*DIM/4 + 255)/256, 256>>>(x,  xh, B_TOK*DIM/4);
    tohalf_kernel<<<(N_CB*DIM/4 + 255)/256, 256>>>(cb, ch, N_CB*DIM/4);
    c2_kernel<<<N_CB/8, dim3(32, 8)>>>(cb);
    vq_kernel<<<B_TOK/MT, NTHREADS, SMEM_TOTAL>>>(x, cb, emb, out);
}

// round 6
// speedup vs baseline: 6.8725x; 1.3383x over previous
#include <cuda_runtime.h>
#include <cuda_fp16.h>
#include <cstdint>

#define B_TOK 16384
#define N_CB  8192
#define DIM   512
#define MT    128          // tokens per CTA
#define NTILE 128          // codes per n-tile
#define KCH   64           // k per chunk
#define KCHUNKS 8          // DIM/KCH
#define TILES (N_CB/NTILE) // 64
#define NTHREADS 512
#define NWARPS  16
#define MARGIN 0.25f
#define CAP   32

// ---- global scratch (no cudaMalloc allowed) ----
__device__ __align__(128) __half g_xh[B_TOK * DIM];
__device__ __align__(128) __half g_ch[N_CB * DIM];
__device__ __align__(128) float  g_c2[N_CB];

// ---- SMEM layout (bytes) ----
#define SM_C2   0          // 128 f32
#define SM_MAX  512        // 128 u32 running max (encoded)
#define SM_CNT  1024       // 128 u32 candidate counts
#define SM_IDX  1536       // 128 u32 final indices
#define SM_LST  2048       // 128 * CAP u32 = 16384
#define SM_A    18432      // 8 chunks x [128 x 64] half (SW128) = 131072
#define SM_B    149504     // 2 bufs x 16384 = 32768
#define SMEM_TOTAL 182272

// ---------------- helpers ----------------
__device__ __forceinline__ uint32_t smem_u32(const void* p) {
    uint32_t a;
    asm("{ .reg .u64 t; cvta.to.shared.u64 t, %1; cvt.u32.u64 %0, t; }" : "=r"(a) : "l"(p));
    return a;
}
__device__ __forceinline__ void cpa16(uint32_t dst, const void* src) {
    asm volatile("cp.async.cg.shared.global [%0], [%1], 16;" :: "r"(dst), "l"(src));
}
__device__ __forceinline__ void cpa_commit() { asm volatile("cp.async.commit_group;" ::: "memory"); }
__device__ __forceinline__ void cpa_wait0()  { asm volatile("cp.async.wait_group 0;"  ::: "memory"); }

__device__ __forceinline__ void ldsm4(uint32_t* r, uint32_t addr) {
    asm volatile("ldmatrix.sync.aligned.m8n8.x4.shared.b16 {%0,%1,%2,%3}, [%4];"
                 : "=r"(r[0]), "=r"(r[1]), "=r"(r[2]), "=r"(r[3]) : "r"(addr));
}
__device__ __forceinline__ void mma16816(float* d, const uint32_t* a, uint32_t b0, uint32_t b1) {
    asm volatile("mma.sync.aligned.m16n8k16.row.col.f32.f16.f16.f32 "
                 "{%0,%1,%2,%3}, {%4,%5,%6,%7}, {%8,%9}, {%0,%1,%2,%3};"
                 : "+f"(d[0]), "+f"(d[1]), "+f"(d[2]), "+f"(d[3])
                 : "r"(a[0]), "r"(a[1]), "r"(a[2]), "r"(a[3]), "r"(b0), "r"(b1));
}

__device__ __forceinline__ uint32_t sw128(uint32_t off) { return off ^ ((off >> 3) & 0x70); }

__device__ __forceinline__ uint32_t enc32(float s) {
    uint32_t u = __float_as_uint(s);
    return (u & 0x80000000u) ? ~u : (u | 0x80000000u);
}
__device__ __forceinline__ float dec32(uint32_t v) {
    return (v & 0x80000000u) ? __uint_as_float(v ^ 0x80000000u) : __uint_as_float(~v);
}
__device__ __forceinline__ unsigned long long pack_key(float t, unsigned n) {
    return ((unsigned long long)enc32(t) << 32) | (unsigned long long)(0xFFFFFFFFu - n);
}

// ---------------- pre-kernels ----------------
__global__ void c2_kernel(const float* __restrict__ cb) {
    int row  = blockIdx.x * blockDim.y + threadIdx.y;
    int lane = threadIdx.x;
    const float4* r = (const float4*)(cb + (size_t)row * DIM);
    float s = 0.f;
#pragma unroll
    for (int i = 0; i < 4; i++) {
        float4 v = r[lane + 32 * i];
        s += v.x*v.x + v.y*v.y + v.z*v.z + v.w*v.w;
    }
#pragma unroll
    for (int off = 16; off > 0; off >>= 1) s += __shfl_down_sync(0xFFFFFFFFu, s, off);
    if (lane == 0) g_c2[row] = s;
}

__global__ void tohalf_kernel(const float* __restrict__ src, __half* __restrict__ dst, int n4) {
    int i = blockIdx.x * blockDim.x + threadIdx.x;
    if (i >= n4) return;
    float4 v = ((const float4*)src)[i];
    ((__half2*)dst)[2*i]   = __floats2half2_rn(v.x, v.y);
    ((__half2*)dst)[2*i+1] = __floats2half2_rn(v.z, v.w);
}

// ---------------- main fused kernel ----------------
__global__ __launch_bounds__(NTHREADS, 1)
void vq_kernel(const float* __restrict__ x, const float* __restrict__ cb,
               const float* __restrict__ emb, float* __restrict__ out) {
    extern __shared__ char smem[];
    const uint32_t sb = smem_u32(smem);
    const int tid  = threadIdx.x;
    const int wid  = tid >> 5;
    const int lane = tid & 31;
    const int m0   = blockIdx.x * MT;
    const int wm   = wid & 3;       // m-group: rows wm*32 .. +31
    const int wn   = wid >> 2;      // n-group: cols wn*32 .. +31

    float*    c2s  = (float*)(smem + SM_C2);
    uint32_t* rmax = (uint32_t*)(smem + SM_MAX);
    uint32_t* cnt  = (uint32_t*)(smem + SM_CNT);
    uint32_t* idxs = (uint32_t*)(smem + SM_IDX);
    uint32_t* lst  = (uint32_t*)(smem + SM_LST);

    if (tid < MT) { rmax[tid] = 0u; cnt[tid] = 0u; }

    // ---- load A (x fp16) into SMEM: 8 chunks of [128 x 64] SW128 ----
    for (int i = tid; i < KCHUNKS * MT * 8; i += NTHREADS) {   // 16B units
        int ch = i >> 10, rem = i & 1023, r = rem >> 3, u = rem & 7;
        cpa16(sb + SM_A + ch * 16384 + sw128(r * 128 + u * 16),
              g_xh + ((size_t)(m0 + r) * DIM + ch * KCH + u * 8));
    }
    cpa_commit();

    // per-thread ldmatrix address components (byte offsets inside a chunk)
    const int rowA[2] = { wm*32 + 0*16 + (lane & 15), wm*32 + 1*16 + (lane & 15) };
    const int kuA = (lane >> 4) * 16;                         // 0 or 16 bytes
    const int rowB = wn*32 + (lane & 7) + ((lane >> 4) << 3); // x4 covers 16 n-rows
    const int kuB = ((lane >> 3) & 1) * 16;

    float acc[2][4][4];

    for (int t = 0; t < TILES; t++) {
        // prefetch B chunk 0 (1024 16B units over 512 threads)
        {
            uint32_t dst = sb + SM_B;
            const __half* src = g_ch + (size_t)(t * NTILE) * DIM;
#pragma unroll
            for (int j = 0; j < 2; j++) {
                int i = tid * 2 + j, r = i >> 3, u = i & 7;
                cpa16(dst + sw128(r * 128 + u * 16), src + (size_t)r * DIM + u * 8);
            }
            cpa_commit();
        }
        if (tid < NTILE) c2s[tid] = g_c2[t * NTILE + tid];

#pragma unroll
        for (int mf = 0; mf < 2; mf++)
#pragma unroll
            for (int nf = 0; nf < 4; nf++)
#pragma unroll
                for (int k = 0; k < 4; k++) acc[mf][nf][k] = 0.f;

        for (int c = 0; c < KCHUNKS; c++) {
            cpa_wait0();
            __syncthreads();                     // chunk c visible to all
            if (c + 1 < KCHUNKS) {               // prefetch next chunk
                uint32_t dst = sb + SM_B + ((c + 1) & 1) * 16384;
                const __half* src = g_ch + (size_t)(t * NTILE) * DIM + (c + 1) * KCH;
#pragma unroll
                for (int j = 0; j < 2; j++) {
                    int i = tid * 2 + j, r = i >> 3, u = i & 7;
                    cpa16(dst + sw128(r * 128 + u * 16), src + (size_t)r * DIM + u * 8);
                }
                cpa_commit();
            }
            uint32_t abase = sb + SM_A + c * 16384;
            uint32_t bbase = sb + SM_B + (c & 1) * 16384;
#pragma unroll
            for (int ks = 0; ks < 4; ks++) {
                uint32_t a[2][4], b[2][4];
#pragma unroll
                for (int mf = 0; mf < 2; mf++)
                    ldsm4(a[mf], abase + sw128(rowA[mf] * 128 + ks * 32 + kuA));
#pragma unroll
                for (int g = 0; g < 2; g++)
                    ldsm4(b[g], bbase + sw128((rowB + g * 16) * 128 + ks * 32 + kuB));
#pragma unroll
                for (int mf = 0; mf < 2; mf++)
#pragma unroll
                    for (int nf = 0; nf < 4; nf++)
                        mma16816(acc[mf][nf], a[mf],
                                 b[nf >> 1][(nf & 1) * 2], b[nf >> 1][(nf & 1) * 2 + 1]);
            }
        }
        __syncthreads();                          // all MMAs done; c2s visible

        // ---- epilogue: running max ----
#pragma unroll
        for (int mf = 0; mf < 2; mf++)
#pragma unroll
            for (int rr = 0; rr < 2; rr++) {
                int row = wm*32 + mf*16 + (lane >> 2) + rr*8;
                float rb = -3.4e38f;
#pragma unroll
                for (int nf = 0; nf < 4; nf++)
#pragma unroll
                    for (int cc = 0; cc < 2; cc++) {
                        int col = wn*32 + nf*8 + (lane & 3)*2 + cc;
                        float s = fmaf(2.f, acc[mf][nf][rr*2 + cc], -c2s[col]);
                        if (s > rb) rb = s;
                    }
                atomicMax(&rmax[row], enc32(rb));
            }
        __syncthreads();

        // ---- admission: candidates within MARGIN of running max ----
#pragma unroll
        for (int mf = 0; mf < 2; mf++)
#pragma unroll
            for (int rr = 0; rr < 2; rr++) {
                int row = wm*32 + mf*16 + (lane >> 2) + rr*8;
                float thr = dec32(rmax[row]) - MARGIN;
#pragma unroll
                for (int nf = 0; nf < 4; nf++)
#pragma unroll
                    for (int cc = 0; cc < 2; cc++) {
                        int col = wn*32 + nf*8 + (lane & 3)*2 + cc;
                        float s = fmaf(2.f, acc[mf][nf][rr*2 + cc], -c2s[col]);
                        if (s >= thr) {
                            uint32_t slot = atomicAdd(&cnt[row], 1u);
                            if (slot < CAP) lst[row * CAP + slot] = (uint32_t)(t * NTILE + col);
                        }
                    }
            }
        __syncthreads();
    }

    // ---- phase 2: exact fp32 rescore of candidates ----
    for (int row = wid; row < MT; row += NWARPS) {
        unsigned n = cnt[row];
        unsigned long long bestk = 0ULL;
        const float* xr = x + (size_t)(m0 + row) * DIM;
        if (n == 0 || n > CAP) {
            for (int code = 0; code < N_CB; code++) {     // exact fallback (never on this data)
                const float* cr = cb + (size_t)code * DIM;
                float p = 0.f;
                for (int e = lane; e < DIM; e += 32) p = fmaf(xr[e], cr[e], p);
#pragma unroll
                for (int off = 16; off > 0; off >>= 1) p += __shfl_xor_sync(0xFFFFFFFFu, p, off);
                unsigned long long k = pack_key(fmaf(2.f, p, -g_c2[code]), (unsigned)code);
                if (k > bestk) bestk = k;
            }
        } else {
            for (unsigned j = 0; j < n; j++) {
                unsigned code = lst[row * CAP + j];
                const float* cr = cb + (size_t)code * DIM;
                float p = 0.f;
#pragma unroll
                for (int e = 0; e < DIM / 32; e++) p = fmaf(xr[lane + 32*e], cr[lane + 32*e], p);
#pragma unroll
                for (int off = 16; off > 0; off >>= 1) p += __shfl_xor_sync(0xFFFFFFFFu, p, off);
                unsigned long long k = pack_key(fmaf(2.f, p, -g_c2[code]), code);
                if (k > bestk) bestk = k;
            }
        }
        if (lane == 0) idxs[row] = 0xFFFFFFFFu - (uint32_t)(bestk & 0xFFFFFFFFu);
    }
    __syncthreads();

    // ---- gather: out[m] = embedding[idx[m]] ----
    const float4* e4 = (const float4*)emb;
    float4* o4 = (float4*)out;
    for (int i = tid; i < MT * (DIM / 4); i += NTHREADS) {
        int m = i >> 7, cc = i & 127;
        o4[(size_t)(m0 + m) * (DIM / 4) + cc] = e4[(size_t)idxs[m] * (DIM / 4) + cc];
    }
}

// ---------------------------------------------------------------------------
extern "C" void kernel_launch(void* const* d_in, const int* in_sizes, int n_in,
                              void* d_out, int out_size) {
    const float* x   = (const float*)d_in[0];
    const float* cb  = (const float*)d_in[1];
    const float* emb = (const float*)d_in[2];
    float* out = (float*)d_out;

    cudaFuncSetAttribute(vq_kernel, cudaFuncAttributeMaxDynamicSharedMemorySize, SMEM_TOTAL);

    __half *xh, *ch;
    cudaGetSymbolAddress((void**)&xh, g_xh);
    cudaGetSymbolAddress((void**)&ch, g_ch);

    tohalf_kernel<<<(B_TOK*DIM/4 + 255)/256, 256>>>(x,  xh, B_TOK*DIM/4);
    tohalf_kernel<<<(N_CB*DIM/4 + 255)/256, 256>>>(cb, ch, N_CB*DIM/4);
    c2_kernel<<<N_CB/8, dim3(32, 8)>>>(cb);
    vq_kernel<<<B_TOK/MT, NTHREADS, SMEM_TOTAL>>>(x, cb, emb, out);
}